// round 8
// baseline (speedup 1.0000x reference)
#include <cuda_runtime.h>

#define T_DIM 4096
#define B_DIM 64
#define H_DIM 256
#define Q_DIM 1024
#define WL    1024
#define KF    31
#define PAD   15

#define N_BLK      296     // 148 SMs x occ 2 — all resident
#define N_GATHER   80      // blocks [0,80) = gather/scatter role
#define N_TILES    512     // 64 b x 8 wTiles
#define N_GUNITS   1024    // 64 b x 16 wc
#define N_SUNITS   256     // 64 b x 4  (1024 floats each)

// ---- scratch (static device globals; no allocation) ----
__device__ float g_qpart[8][B_DIM * H_DIM];
__device__ __align__(16) float g_score[B_DIM * WL];
__device__ __align__(16) float g_align[B_DIM * WL];
__device__ __align__(16) float g_ctxpart[16][B_DIM * H_DIM];
__device__ int g_cntB[B_DIM];     // 8 tiles -> softmax   (self-reset)
__device__ int g_cnt[B_DIM];      // 16 gathers -> ctx-reduce (self-reset)
__device__ int g_rt[B_DIM];       // 20 consumers -> reset bdone (self-reset)
__device__ int g_bdone[B_DIM];    // per-batch align-ready flag
__device__ int g_tickB;           // kB tile ticket (reset by last block)
__device__ int g_done;            // block retire counter (self-reset)

__device__ __forceinline__ float fast_tanh(float x) {
    float e = __expf(2.0f * x);
    return 1.0f - __fdividef(2.0f, e + 1.0f);
}
__device__ __forceinline__ unsigned long long pk2(float x, float y) {
    unsigned long long r;
    asm("mov.b64 %0, {%1,%2};" : "=l"(r) : "f"(x), "f"(y));
    return r;
}
__device__ __forceinline__ void upk2(unsigned long long v, float& x, float& y) {
    asm("mov.b64 {%0,%1}, %2;" : "=f"(x), "=f"(y) : "l"(v));
}
__device__ __forceinline__ void fma2(unsigned long long& d, unsigned long long a, unsigned long long b) {
    asm("fma.rn.f32x2 %0, %1, %2, %3;" : "=l"(d) : "l"(a), "l"(b), "l"(d));
}

// ---------------- Kernel A: q partials ----------------
__global__ void kA(const float* __restrict__ query, const float* __restrict__ wq) {
    __shared__ float q_s[64][33];
    __shared__ float w_s[32][33];
    int tx = threadIdx.x;
    int h0 = blockIdx.x * 32;
    int k0 = blockIdx.y * 128;
    float acc[4][2];
#pragma unroll
    for (int i = 0; i < 4; i++) { acc[i][0] = 0.f; acc[i][1] = 0.f; }
    int hq = tx & 7;
    int bg = tx >> 3;
    for (int s = 0; s < 4; s++) {
        int ks = k0 + s * 32;
        for (int idx = tx; idx < 64 * 32; idx += 256)
            q_s[idx >> 5][idx & 31] = query[(idx >> 5) * Q_DIM + ks + (idx & 31)];
        for (int idx = tx; idx < 32 * 32; idx += 256)
            w_s[idx >> 5][idx & 31] = wq[(h0 + (idx >> 5)) * Q_DIM + ks + (idx & 31)];
        __syncthreads();
#pragma unroll
        for (int kk = 0; kk < 32; kk++) {
            float q0 = q_s[bg * 2 + 0][kk];
            float q1 = q_s[bg * 2 + 1][kk];
#pragma unroll
            for (int i = 0; i < 4; i++) {
                float wv = w_s[hq * 4 + i][kk];
                acc[i][0] += wv * q0;
                acc[i][1] += wv * q1;
            }
        }
        __syncthreads();
    }
#pragma unroll
    for (int i = 0; i < 4; i++)
#pragma unroll
        for (int j = 0; j < 2; j++)
            g_qpart[blockIdx.y][(bg * 2 + j) * H_DIM + h0 + hq * 4 + i] = acc[i][j];
}

// ---------------- Fused persistent kernel ----------------
__global__ void __launch_bounds__(256, 2)
kF(const float* __restrict__ tokens, const float* __restrict__ ca,
   const float* __restrict__ init, const int* __restrict__ wstart,
   const int* __restrict__ num_tokens,
   const float* __restrict__ conv_w, const float* __restrict__ conv_b,
   const float* __restrict__ bq, const float* __restrict__ wsv,
   float* __restrict__ out, int out_size) {
    __shared__ float2 cw2_s[128 * KF];
    __shared__ __align__(16) float loc_s[160];
    __shared__ float qv_s[H_DIM];
    __shared__ float ws_s[H_DIM];
    __shared__ __align__(16) float red[8][128];
    __shared__ float a_s[64];
    __shared__ float4 sh[256];
    __shared__ int sint;

    int tid = threadIdx.x;
    int bid = blockIdx.x;

    if (bid >= N_GATHER) {
        // ===================== compute role: conv tiles + inline softmax =====================
        for (int i = tid; i < 128 * KF; i += 256) {
            int p = i / KF, k = i - p * KF;
            cw2_s[i] = make_float2(conv_w[(2 * p) * KF + k], conv_w[(2 * p + 1) * KF + k]);
        }
        ws_s[tid] = wsv[tid];
        float qbias = bq[tid] + conv_b[tid];
        __syncthreads();

        for (;;) {
            if (tid == 0) sint = atomicAdd(&g_tickB, 1);
            __syncthreads();
            int tau = sint;
            __syncthreads();
            if (tau >= N_TILES) break;
            int b  = tau >> 3;
            int w0 = (tau & 7) * 128;
            int wst = wstart[b];

            {
                float s = qbias;
#pragma unroll
                for (int p = 0; p < 8; p++) s += g_qpart[p][b * H_DIM + tid];
                qv_s[tid] = s;
            }
            float iv = init[b];
            for (int i = tid; i < 160; i += 256) {
                float v = 0.f;
                if (i < 158) {
                    int j = wst + w0 + i;
                    v = (j < PAD) ? iv : ((j < PAD + T_DIM) ? ca[b * T_DIM + (j - PAD)] : 0.f);
                }
                loc_s[i] = v;
            }
            __syncthreads();

            int lane = tid & 31, wi = tid >> 5;
            unsigned long long lwd[34];
#pragma unroll
            for (int j = 0; j < 34; j++) {
                float v = loc_s[lane * 4 + j];
                lwd[j] = pk2(v, v);
            }
            float s0 = 0.f, s1 = 0.f, s2 = 0.f, s3 = 0.f;
            int pbase = wi * 16;
#pragma unroll 1
            for (int pp = 0; pp < 16; pp++) {
                int p = pbase + pp;
                const unsigned long long* cw = (const unsigned long long*)&cw2_s[p * KF];
                unsigned long long a0 = 0ull, a1 = 0ull, a2 = 0ull, a3 = 0ull;
#pragma unroll
                for (int k = 0; k < KF; k++) {
                    unsigned long long w2 = cw[k];
                    fma2(a0, w2, lwd[k + 0]);
                    fma2(a1, w2, lwd[k + 1]);
                    fma2(a2, w2, lwd[k + 2]);
                    fma2(a3, w2, lwd[k + 3]);
                }
                int h0 = 2 * p, h1 = h0 + 1;
                float q0 = qv_s[h0], q1 = qv_s[h1];
                float u0 = ws_s[h0], u1 = ws_s[h1];
                float x, y;
                upk2(a0, x, y); s0 += u0 * fast_tanh(x + q0) + u1 * fast_tanh(y + q1);
                upk2(a1, x, y); s1 += u0 * fast_tanh(x + q0) + u1 * fast_tanh(y + q1);
                upk2(a2, x, y); s2 += u0 * fast_tanh(x + q0) + u1 * fast_tanh(y + q1);
                upk2(a3, x, y); s3 += u0 * fast_tanh(x + q0) + u1 * fast_tanh(y + q1);
            }
            red[wi][lane * 4 + 0] = s0;
            red[wi][lane * 4 + 1] = s1;
            red[wi][lane * 4 + 2] = s2;
            red[wi][lane * 4 + 3] = s3;
            __syncthreads();
            if (tid < 128) {
                float s = 0.f;
#pragma unroll
                for (int p = 0; p < 8; p++) s += red[p][tid];
                g_score[b * WL + w0 + tid] = s;
            }
            __threadfence();
            __syncthreads();
            if (tid == 0) {
                int old = atomicAdd(&g_cntB[b], 1);
                sint = (old == 7);
                if (old == 7) atomicExch(&g_cntB[b], 0);
            }
            __syncthreads();
            if (sint) {
                // ---- inline softmax + argmax + new_ws for batch b ----
                __threadfence();
                float* rv = &red[0][0];
                int*   ri = (int*)&red[2][0];
                float4 sv = *(const float4*)&g_score[b * WL + tid * 4];
                float bv = sv.x; int bi = tid * 4;
                if (sv.y > bv) { bv = sv.y; bi = tid * 4 + 1; }
                if (sv.z > bv) { bv = sv.z; bi = tid * 4 + 2; }
                if (sv.w > bv) { bv = sv.w; bi = tid * 4 + 3; }
                rv[tid] = bv; ri[tid] = bi;
                __syncthreads();
                for (int s = 128; s > 0; s >>= 1) {
                    if (tid < s) {
                        float ov = rv[tid + s]; int oi = ri[tid + s];
                        if (ov > rv[tid] || (ov == rv[tid] && oi < ri[tid])) { rv[tid] = ov; ri[tid] = oi; }
                    }
                    __syncthreads();
                }
                float mx = rv[0];
                int   mi = ri[0];
                __syncthreads();
                float e0 = __expf(sv.x - mx), e1 = __expf(sv.y - mx);
                float e2 = __expf(sv.z - mx), e3 = __expf(sv.w - mx);
                rv[tid] = e0 + e1 + e2 + e3;
                __syncthreads();
                for (int s = 128; s > 0; s >>= 1) {
                    if (tid < s) rv[tid] += rv[tid + s];
                    __syncthreads();
                }
                float inv = __fdividef(1.f, rv[0]);
                float4 av; av.x = e0 * inv; av.y = e1 * inv; av.z = e2 * inv; av.w = e3 * inv;
                *(float4*)&g_align[b * WL + tid * 4] = av;
                if (tid == 0) {
                    int targ = wst + mi;
                    int nw = targ - WL / 2;
                    int lim = num_tokens[b] - WL;
                    if (lim < nw) nw = lim;
                    if (nw < 0) nw = 0;
                    int off = B_DIM * H_DIM + 2 * B_DIM * T_DIM + b;
                    if (off < out_size) out[off] = (float)nw;
                }
                __threadfence();
                __syncthreads();
                if (tid == 0) atomicExch(&g_bdone[b], 1);   // publish align-ready
            }
            __syncthreads();
        }
    } else {
        // ===================== gather/scatter role =====================
        for (int u = bid; u < N_GUNITS; u += N_GATHER) {
            int b = u >> 4, wc = u & 15;
            if (tid == 0) { while (atomicAdd(&g_bdone[b], 0) == 0) __nanosleep(128); }
            __syncthreads();
            __threadfence();
            int wst = wstart[b];
            if (tid < 64) a_s[tid] = g_align[b * WL + wc * 64 + tid];
            __syncthreads();
            int h4 = tid & 63, g = tid >> 6;
            const float4* base = (const float4*)(tokens + (size_t)(wst + wc * 64) * (B_DIM * H_DIM)
                                                 + (size_t)b * H_DIM) + h4;
            float4 acc = make_float4(0.f, 0.f, 0.f, 0.f);
            float4 v[8];
#pragma unroll
            for (int half = 0; half < 2; half++) {
#pragma unroll
                for (int j = 0; j < 8; j++)
                    v[j] = __ldcs(&base[(size_t)(g + 4 * (half * 8 + j)) * (B_DIM * H_DIM / 4)]);
#pragma unroll
                for (int j = 0; j < 8; j++) {
                    float a = a_s[g + 4 * (half * 8 + j)];
                    acc.x += a * v[j].x; acc.y += a * v[j].y;
                    acc.z += a * v[j].z; acc.w += a * v[j].w;
                }
            }
            sh[tid] = acc;
            __syncthreads();
            if (tid < 64) {
                float4 r = sh[tid];
                float4 v1 = sh[tid + 64], v2 = sh[tid + 128], v3 = sh[tid + 192];
                r.x += v1.x + v2.x + v3.x;
                r.y += v1.y + v2.y + v3.y;
                r.z += v1.z + v2.z + v3.z;
                r.w += v1.w + v2.w + v3.w;
                *(float4*)&g_ctxpart[wc][b * H_DIM + h4 * 4] = r;
            }
            __threadfence();
            __syncthreads();
            if (tid == 0) {
                int old = atomicAdd(&g_cnt[b], 1);
                sint = (old == 15);
                if (old == 15) atomicExch(&g_cnt[b], 0);
            }
            __syncthreads();
            if (sint) {
                __threadfence();
                float s = 0.f;
#pragma unroll
                for (int p = 0; p < 16; p++) s += g_ctxpart[p][b * H_DIM + tid];
                int off = b * H_DIM + tid;
                if (off < out_size) out[off] = s;
            }
            __syncthreads();
            if (tid == 0) {
                int o = atomicAdd(&g_rt[b], 1);
                if (o == 19) { atomicExch(&g_bdone[b], 0); atomicExch(&g_rt[b], 0); }
            }
        }
        for (int u = bid; u < N_SUNITS; u += N_GATHER) {
            int b = u >> 2;
            if (tid == 0) { while (atomicAdd(&g_bdone[b], 0) == 0) __nanosleep(128); }
            __syncthreads();
            __threadfence();
            int i4 = u * 256 + tid;
            int i  = i4 * 4;
            int t = i & (T_DIM - 1);
            float4 cav = *(const float4*)&ca[i];
            int ws0 = wstart[b];
            int r0 = t + 0 - ws0, r1 = t + 1 - ws0, r2 = t + 2 - ws0, r3 = t + 3 - ws0;
            float al0 = ((unsigned)r0 < WL) ? g_align[b * WL + r0] : 0.f;
            float al1 = ((unsigned)r1 < WL) ? g_align[b * WL + r1] : 0.f;
            float al2 = ((unsigned)r2 < WL) ? g_align[b * WL + r2] : 0.f;
            float al3 = ((unsigned)r3 < WL) ? g_align[b * WL + r3] : 0.f;
            int cumOff = B_DIM * H_DIM;
            int alOff  = cumOff + B_DIM * T_DIM;
            float4 cum = make_float4(cav.x + al0, cav.y + al1, cav.z + al2, cav.w + al3);
            float4 alv = make_float4(al0, al1, al2, al3);
            if (cumOff + i + 3 < out_size) *(float4*)&out[cumOff + i] = cum;
            if (alOff  + i + 3 < out_size) *(float4*)&out[alOff + i]  = alv;
            __syncthreads();
            if (tid == 0) {
                int o = atomicAdd(&g_rt[b], 1);
                if (o == 19) { atomicExch(&g_bdone[b], 0); atomicExch(&g_rt[b], 0); }
            }
        }
    }
    // global retire: last block resets the tile ticket for the next graph replay
    __syncthreads();
    if (tid == 0) {
        int o = atomicAdd(&g_done, 1);
        if (o == N_BLK - 1) { atomicExch(&g_tickB, 0); atomicExch(&g_done, 0); }
    }
}

extern "C" void kernel_launch(void* const* d_in, const int* in_sizes, int n_in,
                              void* d_out, int out_size) {
    const float* tokens     = (const float*)d_in[0];
    const int*   num_tokens = (const int*)  d_in[2];
    const float* query      = (const float*)d_in[3];
    const float* ca         = (const float*)d_in[4];
    const float* init       = (const float*)d_in[5];
    const int*   wstart     = (const int*)  d_in[6];
    const float* conv_w     = (const float*)d_in[7];
    const float* conv_b     = (const float*)d_in[8];
    const float* wq         = (const float*)d_in[9];
    const float* bq         = (const float*)d_in[10];
    const float* wsv        = (const float*)d_in[11];
    float* out = (float*)d_out;

    kA<<<dim3(8, 8), 256>>>(query, wq);
    kF<<<N_BLK, 256>>>(tokens, ca, init, wstart, num_tokens,
                       conv_w, conv_b, bq, wsv, out, out_size);
}

// round 9
// speedup vs baseline: 1.8502x; 1.8502x over previous
#include <cuda_runtime.h>

#define T_DIM 4096
#define B_DIM 64
#define H_DIM 256
#define Q_DIM 1024
#define WL    1024
#define KF    31
#define PAD   15

// ---- scratch (static device globals; no allocation) ----
__device__ float g_qpart[8][B_DIM * H_DIM];
__device__ __align__(16) float g_score[B_DIM * WL];
__device__ __align__(16) float g_align[B_DIM * WL];
__device__ __align__(16) float g_ctxpart[16][B_DIM * H_DIM];
__device__ int g_cnt[B_DIM];      // kDE retire counters (self-reset)
__device__ int g_cntB[B_DIM];     // kB retire counters (self-reset)

__device__ __forceinline__ float fast_tanh(float x) {
    float e = __expf(2.0f * x);
    return 1.0f - __fdividef(2.0f, e + 1.0f);
}
__device__ __forceinline__ unsigned long long pk2(float x, float y) {
    unsigned long long r;
    asm("mov.b64 %0, {%1,%2};" : "=l"(r) : "f"(x), "f"(y));
    return r;
}
__device__ __forceinline__ void upk2(unsigned long long v, float& x, float& y) {
    asm("mov.b64 {%0,%1}, %2;" : "=f"(x), "=f"(y) : "l"(v));
}
__device__ __forceinline__ void fma2(unsigned long long& d, unsigned long long a, unsigned long long b) {
    asm("fma.rn.f32x2 %0, %1, %2, %3;" : "=l"(d) : "l"(a), "l"(b), "l"(d));
}

// ---------------- Kernel A: q partials  q[b,h] = sum_k query[b,k]*wq[h,k] ----------------
__global__ void kA(const float* __restrict__ query, const float* __restrict__ wq) {
    __shared__ float q_s[64][33];
    __shared__ float w_s[32][33];
    int tx = threadIdx.x;
    int h0 = blockIdx.x * 32;
    int k0 = blockIdx.y * 128;
    float acc[4][2];
#pragma unroll
    for (int i = 0; i < 4; i++) { acc[i][0] = 0.f; acc[i][1] = 0.f; }
    int hq = tx & 7;
    int bg = tx >> 3;
    for (int s = 0; s < 4; s++) {
        int ks = k0 + s * 32;
        for (int idx = tx; idx < 64 * 32; idx += 256)
            q_s[idx >> 5][idx & 31] = query[(idx >> 5) * Q_DIM + ks + (idx & 31)];
        for (int idx = tx; idx < 32 * 32; idx += 256)
            w_s[idx >> 5][idx & 31] = wq[(h0 + (idx >> 5)) * Q_DIM + ks + (idx & 31)];
        __syncthreads();
#pragma unroll
        for (int kk = 0; kk < 32; kk++) {
            float q0 = q_s[bg * 2 + 0][kk];
            float q1 = q_s[bg * 2 + 1][kk];
#pragma unroll
            for (int i = 0; i < 4; i++) {
                float wv = w_s[hq * 4 + i][kk];
                acc[i][0] += wv * q0;
                acc[i][1] += wv * q1;
            }
        }
        __syncthreads();
    }
#pragma unroll
    for (int i = 0; i < 4; i++)
#pragma unroll
        for (int j = 0; j < 2; j++)
            g_qpart[blockIdx.y][(bg * 2 + j) * H_DIM + h0 + hq * 4 + i] = acc[i][j];
}

// ---------------- Kernel B: conv + tanh + score (R4-proven 4w/thread FFMA2)
//                  + absorbed softmax/argmax via per-batch retire counter ----------------
// grid (8 wTiles, 64 b), block 256 (8 warps). Thread = 4 consecutive w; warp owns 16 h-pairs.
__global__ void __launch_bounds__(256, 2)
kB(const float* __restrict__ ca, const float* __restrict__ init,
   const int* __restrict__ wstart, const int* __restrict__ num_tokens,
   const float* __restrict__ conv_w, const float* __restrict__ conv_b,
   const float* __restrict__ bq, const float* __restrict__ wsv,
   float* __restrict__ out, int out_size) {
    __shared__ float2 cw2_s[128 * KF];
    __shared__ __align__(16) float loc_s[160];
    __shared__ float qv_s[H_DIM];
    __shared__ float ws_s[H_DIM];
    __shared__ __align__(16) float red[8][128];
    __shared__ int sflag;

    int tid = threadIdx.x;
    int b   = blockIdx.y;
    int w0  = blockIdx.x * 128;
    int wst = wstart[b];

    for (int i = tid; i < 128 * KF; i += 256) {
        int p = i / KF, k = i - p * KF;
        cw2_s[i] = make_float2(conv_w[(2 * p) * KF + k], conv_w[(2 * p + 1) * KF + k]);
    }
    {
        float s = bq[tid] + conv_b[tid];
#pragma unroll
        for (int p = 0; p < 8; p++) s += g_qpart[p][b * H_DIM + tid];
        qv_s[tid] = s;
        ws_s[tid] = wsv[tid];
    }
    float iv = init[b];
    for (int i = tid; i < 160; i += 256) {
        float v = 0.f;
        if (i < 158) {
            int j = wst + w0 + i;                 // index into padded loc of length T+30
            v = (j < PAD) ? iv : ((j < PAD + T_DIM) ? ca[b * T_DIM + (j - PAD)] : 0.f);
        }
        loc_s[i] = v;
    }
    __syncthreads();

    int lane = tid & 31, wi = tid >> 5;
    unsigned long long lwd[34];                    // duplicated (v,v) loc window
#pragma unroll
    for (int j = 0; j < 34; j++) {
        float v = loc_s[lane * 4 + j];
        lwd[j] = pk2(v, v);
    }

    float s0 = 0.f, s1 = 0.f, s2 = 0.f, s3 = 0.f;
    int pbase = wi * 16;
#pragma unroll 1
    for (int pp = 0; pp < 16; pp++) {
        int p = pbase + pp;
        const unsigned long long* cw = (const unsigned long long*)&cw2_s[p * KF];
        unsigned long long a0 = 0ull, a1 = 0ull, a2 = 0ull, a3 = 0ull;
#pragma unroll
        for (int k = 0; k < KF; k++) {
            unsigned long long w2 = cw[k];         // LDS.64 broadcast
            fma2(a0, w2, lwd[k + 0]);
            fma2(a1, w2, lwd[k + 1]);
            fma2(a2, w2, lwd[k + 2]);
            fma2(a3, w2, lwd[k + 3]);
        }
        int h0 = 2 * p, h1 = h0 + 1;
        float q0 = qv_s[h0], q1 = qv_s[h1];
        float u0 = ws_s[h0], u1 = ws_s[h1];
        float x, y;
        upk2(a0, x, y); s0 += u0 * fast_tanh(x + q0) + u1 * fast_tanh(y + q1);
        upk2(a1, x, y); s1 += u0 * fast_tanh(x + q0) + u1 * fast_tanh(y + q1);
        upk2(a2, x, y); s2 += u0 * fast_tanh(x + q0) + u1 * fast_tanh(y + q1);
        upk2(a3, x, y); s3 += u0 * fast_tanh(x + q0) + u1 * fast_tanh(y + q1);
    }
    red[wi][lane * 4 + 0] = s0;
    red[wi][lane * 4 + 1] = s1;
    red[wi][lane * 4 + 2] = s2;
    red[wi][lane * 4 + 3] = s3;
    __syncthreads();
    if (tid < 128) {
        float s = 0.f;
#pragma unroll
        for (int p = 0; p < 8; p++) s += red[p][tid];
        g_score[b * WL + w0 + tid] = s;
    }

    // ---- retire-counter: last wTile block of batch b runs softmax/argmax/new_ws ----
    __threadfence();
    __syncthreads();
    if (tid == 0) {
        int old = atomicAdd(&g_cntB[b], 1);
        sflag = (old == 7);
        if (old == 7) atomicExch(&g_cntB[b], 0);   // reset for graph replay
    }
    __syncthreads();
    if (!sflag) return;
    __threadfence();

    float* rv = &red[0][0];                        // reuse smem
    int*   ri = (int*)&red[2][0];

    float4 sv = *(const float4*)&g_score[b * WL + tid * 4];
    float bv = sv.x; int bi = tid * 4;
    if (sv.y > bv) { bv = sv.y; bi = tid * 4 + 1; }
    if (sv.z > bv) { bv = sv.z; bi = tid * 4 + 2; }
    if (sv.w > bv) { bv = sv.w; bi = tid * 4 + 3; }
    rv[tid] = bv; ri[tid] = bi;
    __syncthreads();
    for (int s = 128; s > 0; s >>= 1) {
        if (tid < s) {
            float ov = rv[tid + s]; int oi = ri[tid + s];
            if (ov > rv[tid] || (ov == rv[tid] && oi < ri[tid])) { rv[tid] = ov; ri[tid] = oi; }
        }
        __syncthreads();
    }
    float mx = rv[0];
    int   mi = ri[0];
    __syncthreads();

    float e0 = __expf(sv.x - mx), e1 = __expf(sv.y - mx);
    float e2 = __expf(sv.z - mx), e3 = __expf(sv.w - mx);
    rv[tid] = e0 + e1 + e2 + e3;
    __syncthreads();
    for (int s = 128; s > 0; s >>= 1) {
        if (tid < s) rv[tid] += rv[tid + s];
        __syncthreads();
    }
    float inv = __fdividef(1.f, rv[0]);
    float4 av; av.x = e0 * inv; av.y = e1 * inv; av.z = e2 * inv; av.w = e3 * inv;
    *(float4*)&g_align[b * WL + tid * 4] = av;

    if (tid == 0) {
        int targ = wst + mi;
        int nw = targ - WL / 2;
        int lim = num_tokens[b] - WL;
        if (lim < nw) nw = lim;
        if (nw < 0) nw = 0;
        int off = B_DIM * H_DIM + 2 * B_DIM * T_DIM + b;
        if (off < out_size) out[off] = (float)nw;
    }
}

// ---------------- Kernel DE: context gather + finalize + cum/align scatter (R4 exact) ----
__global__ void __launch_bounds__(256)
kDE(const float* __restrict__ tokens, const float* __restrict__ ca,
    const int* __restrict__ wstart, float* __restrict__ out, int out_size) {
    int bx = blockIdx.x, tid = threadIdx.x;

    if (bx < 1024) {
        __shared__ float a_s[64];
        __shared__ float4 sh[256];
        __shared__ int sflag;
        int b = bx >> 4, wc = bx & 15;
        int wst = wstart[b];
        if (tid < 64) a_s[tid] = g_align[b * WL + wc * 64 + tid];
        __syncthreads();
        int h4 = tid & 63, g = tid >> 6;
        const float4* base = (const float4*)(tokens + (size_t)(wst + wc * 64) * (B_DIM * H_DIM)
                                             + (size_t)b * H_DIM) + h4;
        float4 acc = make_float4(0.f, 0.f, 0.f, 0.f);
        float4 v[8];
#pragma unroll
        for (int half = 0; half < 2; half++) {
#pragma unroll
            for (int j = 0; j < 8; j++)
                v[j] = __ldcs(&base[(size_t)(g + 4 * (half * 8 + j)) * (B_DIM * H_DIM / 4)]);
#pragma unroll
            for (int j = 0; j < 8; j++) {
                float a = a_s[g + 4 * (half * 8 + j)];
                acc.x += a * v[j].x; acc.y += a * v[j].y;
                acc.z += a * v[j].z; acc.w += a * v[j].w;
            }
        }
        sh[tid] = acc;
        __syncthreads();
        if (tid < 64) {
            float4 r = sh[tid];
            float4 v1 = sh[tid + 64], v2 = sh[tid + 128], v3 = sh[tid + 192];
            r.x += v1.x + v2.x + v3.x;
            r.y += v1.y + v2.y + v3.y;
            r.z += v1.z + v2.z + v3.z;
            r.w += v1.w + v2.w + v3.w;
            *(float4*)&g_ctxpart[wc][b * H_DIM + h4 * 4] = r;
        }
        __threadfence();
        __syncthreads();
        if (tid == 0) {
            int old = atomicAdd(&g_cnt[b], 1);
            sflag = (old == 15);
            if (old == 15) atomicExch(&g_cnt[b], 0);
        }
        __syncthreads();
        if (sflag) {
            __threadfence();
            float s = 0.f;
#pragma unroll
            for (int p = 0; p < 16; p++) s += g_ctxpart[p][b * H_DIM + tid];
            int off = b * H_DIM + tid;
            if (off < out_size) out[off] = s;
        }
    } else {
        int i4 = (bx - 1024) * 256 + tid;
        int i  = i4 * 4;
        int b = i >> 12, t = i & (T_DIM - 1);
        float4 cav = *(const float4*)&ca[i];
        int ws0 = wstart[b];
        int r0 = t + 0 - ws0, r1 = t + 1 - ws0, r2 = t + 2 - ws0, r3 = t + 3 - ws0;
        float al0 = ((unsigned)r0 < WL) ? g_align[b * WL + r0] : 0.f;
        float al1 = ((unsigned)r1 < WL) ? g_align[b * WL + r1] : 0.f;
        float al2 = ((unsigned)r2 < WL) ? g_align[b * WL + r2] : 0.f;
        float al3 = ((unsigned)r3 < WL) ? g_align[b * WL + r3] : 0.f;
        int cumOff = B_DIM * H_DIM;
        int alOff  = cumOff + B_DIM * T_DIM;
        float4 cum = make_float4(cav.x + al0, cav.y + al1, cav.z + al2, cav.w + al3);
        float4 alv = make_float4(al0, al1, al2, al3);
        if (cumOff + i + 3 < out_size) *(float4*)&out[cumOff + i] = cum;
        if (alOff  + i + 3 < out_size) *(float4*)&out[alOff + i]  = alv;
    }
}

extern "C" void kernel_launch(void* const* d_in, const int* in_sizes, int n_in,
                              void* d_out, int out_size) {
    const float* tokens     = (const float*)d_in[0];
    const int*   num_tokens = (const int*)  d_in[2];
    const float* query      = (const float*)d_in[3];
    const float* ca         = (const float*)d_in[4];
    const float* init       = (const float*)d_in[5];
    const int*   wstart     = (const int*)  d_in[6];
    const float* conv_w     = (const float*)d_in[7];
    const float* conv_b     = (const float*)d_in[8];
    const float* wq         = (const float*)d_in[9];
    const float* bq         = (const float*)d_in[10];
    const float* wsv        = (const float*)d_in[11];
    float* out = (float*)d_out;

    kA<<<dim3(8, 8), 256>>>(query, wq);
    kB<<<dim3(8, 64), 256>>>(ca, init, wstart, num_tokens, conv_w, conv_b, bq, wsv, out, out_size);
    kDE<<<1280, 256>>>(tokens, ca, wstart, out, out_size);
}

// round 10
// speedup vs baseline: 2.2167x; 1.1981x over previous
#include <cuda_runtime.h>

#define T_DIM 4096
#define B_DIM 64
#define H_DIM 256
#define Q_DIM 1024
#define WL    1024
#define KF    31
#define PAD   15

#define NKP 16   // kA k-split partials

// ---- scratch (static device globals; no allocation) ----
__device__ float g_qpart[NKP][B_DIM * H_DIM];
__device__ __align__(16) float g_score[B_DIM * WL];
__device__ __align__(16) float g_align[B_DIM * WL];
__device__ __align__(16) float g_ctxpart[16][B_DIM * H_DIM];
__device__ int g_cnt[B_DIM];      // kDE retire counters (self-reset)

__device__ __forceinline__ float fast_tanh(float x) {
    float e = __expf(2.0f * x);
    return 1.0f - __fdividef(2.0f, e + 1.0f);
}
__device__ __forceinline__ unsigned long long pk2(float x, float y) {
    unsigned long long r;
    asm("mov.b64 %0, {%1,%2};" : "=l"(r) : "f"(x), "f"(y));
    return r;
}
__device__ __forceinline__ void upk2(unsigned long long v, float& x, float& y) {
    asm("mov.b64 {%0,%1}, %2;" : "=f"(x), "=f"(y) : "l"(v));
}
__device__ __forceinline__ void fma2(unsigned long long& d, unsigned long long a, unsigned long long b) {
    asm("fma.rn.f32x2 %0, %1, %2, %3;" : "=l"(d) : "l"(a), "l"(b), "l"(d));
}

// ---------------- Kernel A: q partials  q[b,h] = sum_k query[b,k]*wq[h,k] ----------------
// grid (8 hTiles, 16 kChunks) = 128 blocks, block 256. Single smem stage, one barrier.
// Block tile: 32 h x 64 b x 64 k.
__global__ void __launch_bounds__(256)
kA(const float* __restrict__ query, const float* __restrict__ wq) {
    __shared__ float q_s[64][65];
    __shared__ float w_s[32][65];
    int tx = threadIdx.x;
    int h0 = blockIdx.x * 32;
    int k0 = blockIdx.y * 64;

    // one-shot fill: 4 q-float4 + 2 w-float4 per thread (independent, MLP=6)
#pragma unroll
    for (int i = tx; i < 64 * 16; i += 256) {
        int bb = i >> 4, c = (i & 15) * 4;
        float4 v = *(const float4*)&query[bb * Q_DIM + k0 + c];
        q_s[bb][c + 0] = v.x; q_s[bb][c + 1] = v.y;
        q_s[bb][c + 2] = v.z; q_s[bb][c + 3] = v.w;
    }
#pragma unroll
    for (int i = tx; i < 32 * 16; i += 256) {
        int hh = i >> 4, c = (i & 15) * 4;
        float4 v = *(const float4*)&wq[(h0 + hh) * Q_DIM + k0 + c];
        w_s[hh][c + 0] = v.x; w_s[hh][c + 1] = v.y;
        w_s[hh][c + 2] = v.z; w_s[hh][c + 3] = v.w;
    }
    __syncthreads();

    int hq = tx & 7;        // 8 groups of 4 h
    int bg = tx >> 3;       // 32 groups of 2 b
    float acc[4][2];
#pragma unroll
    for (int i = 0; i < 4; i++) { acc[i][0] = 0.f; acc[i][1] = 0.f; }
#pragma unroll 8
    for (int kk = 0; kk < 64; kk++) {
        float q0 = q_s[bg * 2 + 0][kk];
        float q1 = q_s[bg * 2 + 1][kk];
#pragma unroll
        for (int i = 0; i < 4; i++) {
            float wv = w_s[hq * 4 + i][kk];
            acc[i][0] += wv * q0;
            acc[i][1] += wv * q1;
        }
    }
#pragma unroll
    for (int i = 0; i < 4; i++)
#pragma unroll
        for (int j = 0; j < 2; j++)
            g_qpart[blockIdx.y][(bg * 2 + j) * H_DIM + h0 + hq * 4 + i] = acc[i][j];
}

// ---------------- Kernel B: conv + tanh + score (R4-proven 4w/thread FFMA2) ----------------
// grid (8 wTiles, 64 b), block 256 (8 warps). Thread = 4 consecutive w; warp owns 16 h-pairs.
__global__ void __launch_bounds__(256, 2)
kB(const float* __restrict__ ca, const float* __restrict__ init,
   const int* __restrict__ wstart,
   const float* __restrict__ conv_w, const float* __restrict__ conv_b,
   const float* __restrict__ bq, const float* __restrict__ wsv) {
    __shared__ float2 cw2_s[128 * KF];
    __shared__ __align__(16) float loc_s[160];
    __shared__ float qv_s[H_DIM];
    __shared__ float ws_s[H_DIM];
    __shared__ float red[8][128];

    int tid = threadIdx.x;
    int b   = blockIdx.y;
    int w0  = blockIdx.x * 128;
    int wst = wstart[b];

    for (int i = tid; i < 128 * KF; i += 256) {
        int p = i / KF, k = i - p * KF;
        cw2_s[i] = make_float2(conv_w[(2 * p) * KF + k], conv_w[(2 * p + 1) * KF + k]);
    }
    {
        float s = bq[tid] + conv_b[tid];
#pragma unroll
        for (int p = 0; p < NKP; p++) s += g_qpart[p][b * H_DIM + tid];
        qv_s[tid] = s;
        ws_s[tid] = wsv[tid];
    }
    float iv = init[b];
    for (int i = tid; i < 160; i += 256) {
        float v = 0.f;
        if (i < 158) {
            int j = wst + w0 + i;                 // index into padded loc of length T+30
            v = (j < PAD) ? iv : ((j < PAD + T_DIM) ? ca[b * T_DIM + (j - PAD)] : 0.f);
        }
        loc_s[i] = v;
    }
    __syncthreads();

    int lane = tid & 31, wi = tid >> 5;
    unsigned long long lwd[34];                    // duplicated (v,v) loc window
#pragma unroll
    for (int j = 0; j < 34; j++) {
        float v = loc_s[lane * 4 + j];
        lwd[j] = pk2(v, v);
    }

    float s0 = 0.f, s1 = 0.f, s2 = 0.f, s3 = 0.f;
    int pbase = wi * 16;
#pragma unroll 1
    for (int pp = 0; pp < 16; pp++) {
        int p = pbase + pp;
        const unsigned long long* cw = (const unsigned long long*)&cw2_s[p * KF];
        unsigned long long a0 = 0ull, a1 = 0ull, a2 = 0ull, a3 = 0ull;
#pragma unroll
        for (int k = 0; k < KF; k++) {
            unsigned long long w2 = cw[k];         // LDS.64 broadcast
            fma2(a0, w2, lwd[k + 0]);
            fma2(a1, w2, lwd[k + 1]);
            fma2(a2, w2, lwd[k + 2]);
            fma2(a3, w2, lwd[k + 3]);
        }
        int h0 = 2 * p, h1 = h0 + 1;
        float q0 = qv_s[h0], q1 = qv_s[h1];
        float u0 = ws_s[h0], u1 = ws_s[h1];
        float x, y;
        upk2(a0, x, y); s0 += u0 * fast_tanh(x + q0) + u1 * fast_tanh(y + q1);
        upk2(a1, x, y); s1 += u0 * fast_tanh(x + q0) + u1 * fast_tanh(y + q1);
        upk2(a2, x, y); s2 += u0 * fast_tanh(x + q0) + u1 * fast_tanh(y + q1);
        upk2(a3, x, y); s3 += u0 * fast_tanh(x + q0) + u1 * fast_tanh(y + q1);
    }
    red[wi][lane * 4 + 0] = s0;
    red[wi][lane * 4 + 1] = s1;
    red[wi][lane * 4 + 2] = s2;
    red[wi][lane * 4 + 3] = s3;
    __syncthreads();
    if (tid < 128) {
        float s = 0.f;
#pragma unroll
        for (int p = 0; p < 8; p++) s += red[p][tid];
        g_score[b * WL + w0 + tid] = s;
    }
}

// ---------------- Kernel C: softmax + argmax + new_ws ----------------
__global__ void kC(const int* __restrict__ wstart, const int* __restrict__ num_tokens,
                   float* __restrict__ out, int out_size) {
    __shared__ float rv[256];
    __shared__ int   ri[256];
    int tid = threadIdx.x, b = blockIdx.x;

    float4 sv = *(const float4*)&g_score[b * WL + tid * 4];
    float bv = sv.x; int bi = tid * 4;
    if (sv.y > bv) { bv = sv.y; bi = tid * 4 + 1; }
    if (sv.z > bv) { bv = sv.z; bi = tid * 4 + 2; }
    if (sv.w > bv) { bv = sv.w; bi = tid * 4 + 3; }
    rv[tid] = bv; ri[tid] = bi;
    __syncthreads();
    for (int s = 128; s > 0; s >>= 1) {
        if (tid < s) {
            float ov = rv[tid + s]; int oi = ri[tid + s];
            if (ov > rv[tid] || (ov == rv[tid] && oi < ri[tid])) { rv[tid] = ov; ri[tid] = oi; }
        }
        __syncthreads();
    }
    float mx = rv[0];
    int   mi = ri[0];
    __syncthreads();

    float e0 = __expf(sv.x - mx), e1 = __expf(sv.y - mx);
    float e2 = __expf(sv.z - mx), e3 = __expf(sv.w - mx);
    rv[tid] = e0 + e1 + e2 + e3;
    __syncthreads();
    for (int s = 128; s > 0; s >>= 1) {
        if (tid < s) rv[tid] += rv[tid + s];
        __syncthreads();
    }
    float inv = __fdividef(1.f, rv[0]);
    float4 av; av.x = e0 * inv; av.y = e1 * inv; av.z = e2 * inv; av.w = e3 * inv;
    *(float4*)&g_align[b * WL + tid * 4] = av;

    if (tid == 0) {
        int targ = wstart[b] + mi;
        int nw = targ - WL / 2;
        int lim = num_tokens[b] - WL;
        if (lim < nw) nw = lim;
        if (nw < 0) nw = 0;
        int off = B_DIM * H_DIM + 2 * B_DIM * T_DIM + b;
        if (off < out_size) out[off] = (float)nw;
    }
}

// ---------------- Kernel DE: context gather + finalize + cum/align scatter (R4 exact) ----
__global__ void __launch_bounds__(256)
kDE(const float* __restrict__ tokens, const float* __restrict__ ca,
    const int* __restrict__ wstart, float* __restrict__ out, int out_size) {
    int bx = blockIdx.x, tid = threadIdx.x;

    if (bx < 1024) {
        __shared__ float a_s[64];
        __shared__ float4 sh[256];
        __shared__ int sflag;
        int b = bx >> 4, wc = bx & 15;
        int wst = wstart[b];
        if (tid < 64) a_s[tid] = g_align[b * WL + wc * 64 + tid];
        __syncthreads();
        int h4 = tid & 63, g = tid >> 6;
        const float4* base = (const float4*)(tokens + (size_t)(wst + wc * 64) * (B_DIM * H_DIM)
                                             + (size_t)b * H_DIM) + h4;
        float4 acc = make_float4(0.f, 0.f, 0.f, 0.f);
        float4 v[8];
#pragma unroll
        for (int half = 0; half < 2; half++) {
#pragma unroll
            for (int j = 0; j < 8; j++)
                v[j] = __ldcs(&base[(size_t)(g + 4 * (half * 8 + j)) * (B_DIM * H_DIM / 4)]);
#pragma unroll
            for (int j = 0; j < 8; j++) {
                float a = a_s[g + 4 * (half * 8 + j)];
                acc.x += a * v[j].x; acc.y += a * v[j].y;
                acc.z += a * v[j].z; acc.w += a * v[j].w;
            }
        }
        sh[tid] = acc;
        __syncthreads();
        if (tid < 64) {
            float4 r = sh[tid];
            float4 v1 = sh[tid + 64], v2 = sh[tid + 128], v3 = sh[tid + 192];
            r.x += v1.x + v2.x + v3.x;
            r.y += v1.y + v2.y + v3.y;
            r.z += v1.z + v2.z + v3.z;
            r.w += v1.w + v2.w + v3.w;
            *(float4*)&g_ctxpart[wc][b * H_DIM + h4 * 4] = r;
        }
        __threadfence();
        __syncthreads();
        if (tid == 0) {
            int old = atomicAdd(&g_cnt[b], 1);
            sflag = (old == 15);
            if (old == 15) atomicExch(&g_cnt[b], 0);
        }
        __syncthreads();
        if (sflag) {
            __threadfence();
            float s = 0.f;
#pragma unroll
            for (int p = 0; p < 16; p++) s += g_ctxpart[p][b * H_DIM + tid];
            int off = b * H_DIM + tid;
            if (off < out_size) out[off] = s;
        }
    } else {
        int i4 = (bx - 1024) * 256 + tid;
        int i  = i4 * 4;
        int b = i >> 12, t = i & (T_DIM - 1);
        float4 cav = *(const float4*)&ca[i];
        int ws0 = wstart[b];
        int r0 = t + 0 - ws0, r1 = t + 1 - ws0, r2 = t + 2 - ws0, r3 = t + 3 - ws0;
        float al0 = ((unsigned)r0 < WL) ? g_align[b * WL + r0] : 0.f;
        float al1 = ((unsigned)r1 < WL) ? g_align[b * WL + r1] : 0.f;
        float al2 = ((unsigned)r2 < WL) ? g_align[b * WL + r2] : 0.f;
        float al3 = ((unsigned)r3 < WL) ? g_align[b * WL + r3] : 0.f;
        int cumOff = B_DIM * H_DIM;
        int alOff  = cumOff + B_DIM * T_DIM;
        float4 cum = make_float4(cav.x + al0, cav.y + al1, cav.z + al2, cav.w + al3);
        float4 alv = make_float4(al0, al1, al2, al3);
        if (cumOff + i + 3 < out_size) *(float4*)&out[cumOff + i] = cum;
        if (alOff  + i + 3 < out_size) *(float4*)&out[alOff + i]  = alv;
    }
}

extern "C" void kernel_launch(void* const* d_in, const int* in_sizes, int n_in,
                              void* d_out, int out_size) {
    const float* tokens     = (const float*)d_in[0];
    const int*   num_tokens = (const int*)  d_in[2];
    const float* query      = (const float*)d_in[3];
    const float* ca         = (const float*)d_in[4];
    const float* init       = (const float*)d_in[5];
    const int*   wstart     = (const int*)  d_in[6];
    const float* conv_w     = (const float*)d_in[7];
    const float* conv_b     = (const float*)d_in[8];
    const float* wq         = (const float*)d_in[9];
    const float* bq         = (const float*)d_in[10];
    const float* wsv        = (const float*)d_in[11];
    float* out = (float*)d_out;

    kA<<<dim3(8, NKP), 256>>>(query, wq);
    kB<<<dim3(8, 64), 256>>>(ca, init, wstart, conv_w, conv_b, bq, wsv);
    kC<<<64, 256>>>(wstart, num_tokens, out, out_size);
    kDE<<<1280, 256>>>(tokens, ca, wstart, out, out_size);
}